// round 14
// baseline (speedup 1.0000x reference)
#include <cuda_runtime.h>
#include <cuda_bf16.h>
#include <cuda_fp16.h>
#include <cstdint>

#define B_    8
#define S_    1029
#define D_    1024
#define H_    16
#define HD_   64
#define M_    (B_*S_)     // 8232
#define MPAD  8320        // 65 * 128
#define NPFX  5
#define SCALE_ 0.125f
#define SVP   1088        // padded key-stride for transposed V

// ---------------------------------------------------------------------------
// Scratch (device globals — no allocation allowed). .bss zero-init.
// ---------------------------------------------------------------------------
__device__ __align__(16) __half g_qh[B_*H_*S_*HD_];     // fp16 Q (pre->post rope in place)
__device__ __align__(16) __half g_kh[B_*H_*S_*HD_];     // fp16 K
__device__ __align__(16) __half g_vth[B_*H_*HD_*SVP];   // V^T [b,h,d,s]

__device__ __align__(16) __half g_xhi [MPAD*D_];
__device__ __align__(16) __half g_aohi[MPAD*D_];  // attn out (fp16) [m,n]
__device__ __align__(16) __half g_wthi[4*D_*D_];  // W^T, [w][n][k]

// ---------------------------------------------------------------------------
// mma.sync helpers (portable PTX)
// ---------------------------------------------------------------------------
__device__ __forceinline__ uint32_t smem_u32(const void* p) {
    uint32_t a;
    asm("{ .reg .u64 t; cvta.to.shared.u64 t, %1; cvt.u32.u64 %0, t; }"
        : "=r"(a) : "l"(p));
    return a;
}
__device__ __forceinline__ void ldsm4(uint32_t* r, uint32_t addr) {
    asm volatile("ldmatrix.sync.aligned.m8n8.x4.shared.b16 {%0,%1,%2,%3}, [%4];"
        : "=r"(r[0]), "=r"(r[1]), "=r"(r[2]), "=r"(r[3]) : "r"(addr));
}
__device__ __forceinline__ void mmah16816(float* c, const uint32_t* a,
                                          const uint32_t* b) {
    asm volatile(
        "mma.sync.aligned.m16n8k16.row.col.f32.f16.f16.f32 "
        "{%0,%1,%2,%3}, {%4,%5,%6,%7}, {%8,%9}, {%0,%1,%2,%3};"
        : "+f"(c[0]), "+f"(c[1]), "+f"(c[2]), "+f"(c[3])
        : "r"(a[0]), "r"(a[1]), "r"(a[2]), "r"(a[3]), "r"(b[0]), "r"(b[1]));
}

// ---------------------------------------------------------------------------
// Round x to fp16.
// ---------------------------------------------------------------------------
__global__ void split_act(const float* __restrict__ src)
{
    const int total4 = M_ * D_ / 4;
    int i = blockIdx.x * blockDim.x + threadIdx.x;
    if (i >= total4) return;
    float4 v = ((const float4*)src)[i];
    __half2* Hi = (__half2*)g_xhi;
    Hi[2*i]   = __halves2half2(__float2half_rn(v.x), __float2half_rn(v.y));
    Hi[2*i+1] = __halves2half2(__float2half_rn(v.z), __float2half_rn(v.w));
}

// ---------------------------------------------------------------------------
// Transpose + round all 4 weights (blockIdx.z = widx).
// ---------------------------------------------------------------------------
__global__ void split_w(const float* __restrict__ W0, const float* __restrict__ W1,
                        const float* __restrict__ W2, const float* __restrict__ W3)
{
    __shared__ float t[32][33];
    int widx = blockIdx.z;
    const float* W = (widx == 0) ? W0 : (widx == 1) ? W1 : (widx == 2) ? W2 : W3;
    int n0 = blockIdx.x * 32, k0 = blockIdx.y * 32;
    int tx = threadIdx.x, ty = threadIdx.y;   // 32 x 8
    #pragma unroll
    for (int i = 0; i < 4; i++)
        t[ty + 8*i][tx] = W[(size_t)(k0 + ty + 8*i) * D_ + n0 + tx];
    __syncthreads();
    __half* Hi = g_wthi + (size_t)widx * D_ * D_;
    #pragma unroll
    for (int i = 0; i < 4; i++) {
        float v = t[tx][ty + 8*i];
        Hi[(size_t)(n0 + ty + 8*i) * D_ + k0 + tx] = __float2half_rn(v);
    }
}

// ---------------------------------------------------------------------------
// fp16 tensor-core GEMM: C = A * B. 32 chunks, BK=32, double-buffered 40KB.
// mode 0 -> dst fp32; 1/2 -> g_qh/g_kh fp16; 3 -> fp16 V^T.
// mode == -1: fused QKV; grid.y spans 24, w = by>>3 selects weight & output.
// ---------------------------------------------------------------------------
#define ASTRIDE 40
#define TILEB (128*ASTRIDE)
#define GEMM_SMEM (2*2*TILEB*2)             // 40960 bytes

__global__ __launch_bounds__(256) void mma_gemm(
    int asel, int widx, const float* __restrict__ bq_,
    const float* __restrict__ bv_, float* __restrict__ dst, int mode)
{
    extern __shared__ __half smg[];         // [2][2][TILEB]: A,B

    const int tid  = threadIdx.x;
    const int lane = tid & 31, wid = tid >> 5;
    const int wm = wid & 1, wn = wid >> 1;
    const int bm = blockIdx.x * 128;

    int bn, emode;
    const float* bias;
    if (mode == -1) {               // fused QKV
        int w = blockIdx.y >> 3;
        bn    = (blockIdx.y & 7) * 128;
        widx  = w;
        emode = 1 + w;              // 1=q, 2=k, 3=v
        bias  = (w == 0) ? bq_ : (w == 2) ? bv_ : nullptr;
    } else {
        bn    = blockIdx.y * 128;
        emode = mode;
        bias  = bq_;
    }

    const __half* A = asel ? g_aohi : g_xhi;
    const __half* Bw = g_wthi + (size_t)widx * D_ * D_;

    float acc[4][4][4] = {};

    #pragma unroll
    for (int it = 0; it < 2; it++) {
        int idx = tid + it * 256;
        int r = idx >> 2, c8 = (idx & 3) * 8;
        *(uint4*)&smg[0*TILEB + r*ASTRIDE + c8] =
            *(const uint4*)(A + (size_t)(bm + r) * D_ + c8);
        *(uint4*)&smg[1*TILEB + r*ASTRIDE + c8] =
            *(const uint4*)(Bw + (size_t)(bn + r) * D_ + c8);
    }
    __syncthreads();

    const uint32_t smB = smem_u32(smg);
    const uint32_t aOff = (uint32_t)(wm*64 + (lane & 15)) * 80 + (lane >> 4) * 16;
    const uint32_t bOff = (uint32_t)(wn*32 + (lane & 7) + ((lane >> 4) << 3)) * 80
                          + ((lane >> 3) & 1) * 16;
    const uint32_t TB = TILEB * 2;
    const uint32_t BUFB = 2 * TB;

    const int NCH = 32;
    uint4 p[4];
    for (int t = 0; t < NCH; t++) {
        int buf = t & 1;
        if (t + 1 < NCH) {
            int k0 = (t + 1) * 32;
            #pragma unroll
            for (int it = 0; it < 2; it++) {
                int idx = tid + it * 256;
                int r = idx >> 2, c8 = (idx & 3) * 8;
                p[it*2 + 0] = *(const uint4*)(A  + (size_t)(bm + r) * D_ + k0 + c8);
                p[it*2 + 1] = *(const uint4*)(Bw + (size_t)(bn + r) * D_ + k0 + c8);
            }
        }
        uint32_t aB = smB + buf * BUFB;
        uint32_t bB = aB + TB;
        #pragma unroll
        for (int ks = 0; ks < 2; ks++) {
            uint32_t af[4][4], bf[2][4];
            #pragma unroll
            for (int mt = 0; mt < 4; mt++)
                ldsm4(af[mt], aB + aOff + mt * 16 * 80 + ks * 32);
            #pragma unroll
            for (int bt = 0; bt < 2; bt++)
                ldsm4(bf[bt], bB + bOff + bt * 16 * 80 + ks * 32);
            #pragma unroll
            for (int mt = 0; mt < 4; mt++)
                #pragma unroll
                for (int nt = 0; nt < 4; nt++)
                    mmah16816(acc[mt][nt], af[mt], &bf[nt >> 1][(nt & 1) * 2]);
        }
        if (t + 1 < NCH) {
            int nb = buf ^ 1;
            __half* d0 = smg + nb * 2 * TILEB;
            #pragma unroll
            for (int it = 0; it < 2; it++) {
                int idx = tid + it * 256;
                int r = idx >> 2, c8 = (idx & 3) * 8;
                *(uint4*)&d0[0*TILEB + r*ASTRIDE + c8] = p[it*2 + 0];
                *(uint4*)&d0[1*TILEB + r*ASTRIDE + c8] = p[it*2 + 1];
            }
        }
        __syncthreads();
    }

    const int rg = lane >> 2, cp = (lane & 3) * 2;
    #pragma unroll
    for (int mt = 0; mt < 4; mt++) {
        #pragma unroll
        for (int nt = 0; nt < 4; nt++) {
            int n = bn + wn*32 + nt*8 + cp;
            float b0v = bias ? __ldg(bias + n)     : 0.f;
            float b1v = bias ? __ldg(bias + n + 1) : 0.f;
            #pragma unroll
            for (int h2 = 0; h2 < 2; h2++) {
                int m = bm + wm*64 + mt*16 + rg + h2*8;
                if (m >= M_) continue;
                float v0 = acc[mt][nt][h2*2 + 0] + b0v;
                float v1 = acc[mt][nt][h2*2 + 1] + b1v;
                if (emode == 0) {
                    dst[(size_t)m * D_ + n]     = v0;
                    dst[(size_t)m * D_ + n + 1] = v1;
                } else if (emode == 3) {
                    int b = m / S_, s = m % S_;
                    int h = n >> 6, d = n & 63;
                    size_t o = ((size_t)(b * H_ + h) * HD_ + d) * SVP + s;
                    g_vth[o]       = __float2half_rn(v0);
                    g_vth[o + SVP] = __float2half_rn(v1);
                } else {
                    // q/k: write fp16 pairs (rope applied in place later)
                    int b = m / S_, s = m % S_;
                    int h = n >> 6, d = n & 63;
                    __half* g = (emode == 1) ? g_qh : g_kh;
                    size_t o = (((size_t)(b * H_ + h)) * S_ + s) * HD_ + d;
                    *(__half2*)&g[o] = __halves2half2(
                        __float2half_rn(v0), __float2half_rn(v1));
                }
            }
        }
    }
}

// ---------------------------------------------------------------------------
// In-place fp16 RoPE (patch tokens) + q-scale. Thread owns (d2,d2+1) and
// (d2+32,d2+33) — reads both half2s before writing (in-place safe).
// ---------------------------------------------------------------------------
__global__ void rope_kernel(const float* __restrict__ cosp,
                            const float* __restrict__ sinp)
{
    const int total = B_*H_*S_*16;
    int i = blockIdx.x * blockDim.x + threadIdx.x;
    if (i >= total) return;
    const bool isQ = (blockIdx.y == 0);
    int d2 = (i & 15) * 2;
    int s  = (i >> 4) % S_;
    int bh = i / (16 * S_);
    __half* Hp = (isQ ? g_qh : g_kh) + ((size_t)bh * S_ + s) * HD_;

    __half2 a = *(__half2*)&Hp[d2];        // d2, d2+1
    __half2 b = *(__half2*)&Hp[d2 + 32];   // d2+32, d2+33
    float x0 = __half2float(__low2half(a)),  x1 = __half2float(__high2half(a));
    float z0 = __half2float(__low2half(b)),  z1 = __half2float(__high2half(b));
    float y0, y1, w0, w1;
    if (s < NPFX) {
        y0 = x0; y1 = x1; w0 = z0; w1 = z1;
    } else {
        int p = s - NPFX;
        float2 cA = *(const float2*)&cosp[p*HD_ + d2];
        float2 cB = *(const float2*)&cosp[p*HD_ + d2 + 32];
        float2 sA = *(const float2*)&sinp[p*HD_ + d2];
        float2 sB = *(const float2*)&sinp[p*HD_ + d2 + 32];
        y0 = x0*cA.x - z0*sA.x;   // d < 32 : x*cos - x[d+32]*sin
        y1 = x1*cA.y - z1*sA.y;
        w0 = z0*cB.x + x0*sB.x;   // d >= 32: x*cos + x[d-32]*sin
        w1 = z1*cB.y + x1*sB.y;
    }
    if (isQ) { y0 *= SCALE_; y1 *= SCALE_; w0 *= SCALE_; w1 *= SCALE_; }
    *(__half2*)&Hp[d2]      = __halves2half2(__float2half_rn(y0), __float2half_rn(y1));
    *(__half2*)&Hp[d2 + 32] = __halves2half2(__float2half_rn(w0), __float2half_rn(w1));
}

// ---------------------------------------------------------------------------
// Tensor-core flash attention, 128-q x 64-k tiles, register-resident softmax.
// 8 warps in 2(q)x4(k). No fp32 S smem buffer.
// ---------------------------------------------------------------------------
#define QST 72
// Qhi[128]+Khi[64]+Vthi[64]+Pm[128] rows x QST halves + reductions
#define ATT_SMEM ((128+64+64+128)*QST*2 + (3*128 + 2*512)*4)   // 60928

__global__ __launch_bounds__(256) void attn_kernel()
{
    extern __shared__ char smx[];
    __half* Qhi  = (__half*)smx;            // [128][QST]  (q, d)
    __half* Khi  = Qhi  + 128*QST;          // [64][QST]   (key, d)
    __half* Vthi = Khi  + 64*QST;           // [64][QST]   (d, key)
    __half* Pm   = Vthi + 64*QST;           // [128][QST]  (q, key)
    float*  m_s  = (float*)(Pm + 128*QST);  // [128]
    float*  l_s  = m_s + 128;
    float*  al_s = l_s + 128;
    float*  redm = al_s + 128;              // [4][128] per-k-warp row max
    float*  reds = redm + 512;              // [4][128] per-k-warp row sum

    const int tid  = threadIdx.x;
    const int lane = tid & 31, wid = tid >> 5;
    const int wm = wid & 1, wn = wid >> 1;     // 2(q) x 4(k)
    const int rg = lane >> 2, cp = (lane & 3) * 2;
    const int bh = blockIdx.y;
    const int m0 = blockIdx.x * 128;
    const __half* qhp = g_qh + (size_t)bh * S_ * HD_;
    const __half* khp = g_kh + (size_t)bh * S_ * HD_;
    const __half* vhp = g_vth + (size_t)bh * HD_ * SVP;

    const uint4 Z4 = make_uint4(0u, 0u, 0u, 0u);
    #pragma unroll
    for (int it = 0; it < 4; it++) {
        int idx = tid + it * 256;
        int r = idx >> 3, c8 = (idx & 7) * 8;
        uint4 vh = Z4;
        if (m0 + r < S_)
            vh = *(const uint4*)(qhp + (size_t)(m0 + r) * HD_ + c8);
        *(uint4*)&Qhi[r*QST + c8] = vh;
    }
    if (tid < 128) { m_s[tid] = -1e30f; l_s[tid] = 0.f; }

    const uint32_t QhiB = smem_u32(Qhi);
    const uint32_t KhiB = smem_u32(Khi);
    const uint32_t VhiB = smem_u32(Vthi);
    const uint32_t PmB  = smem_u32(Pm);
    const uint32_t aOff = (uint32_t)(wm*64 + (lane & 15)) * 144 + (lane >> 4) * 16;
    const uint32_t bOff = (uint32_t)(wn*16 + (lane & 7) + ((lane >> 4) << 3)) * 144
                          + ((lane >> 3) & 1) * 16;

    float oacc[4][2][4] = {};

    for (int n0 = 0; n0 < S_; n0 += 64) {
        __syncthreads();   // protects K/V/Pm reuse + first-iter init
        #pragma unroll
        for (int it = 0; it < 2; it++) {
            int idx = tid + it * 256;
            int r = idx >> 3, c8 = (idx & 7) * 8;
            uint4 vh = Z4;
            if (n0 + r < S_)
                vh = *(const uint4*)(khp + (size_t)(n0 + r) * HD_ + c8);
            *(uint4*)&Khi[r*QST + c8] = vh;
        }
        #pragma unroll
        for (int it = 0; it < 2; it++) {
            int idx = tid + it * 256;
            int d = idx >> 3, k8 = (idx & 7) * 8;
            *(uint4*)&Vthi[d*QST + k8] =
                *(const uint4*)(vhp + (size_t)d * SVP + n0 + k8);
        }
        __syncthreads();

        // S = Q K^T (fragments stay in registers)
        float sacc[4][2][4] = {};
        #pragma unroll
        for (int ks = 0; ks < 4; ks++) {
            uint32_t ah[4][4], bhh[4];
            #pragma unroll
            for (int mt = 0; mt < 4; mt++)
                ldsm4(ah[mt], QhiB + aOff + mt * 16 * 144 + ks * 32);
            ldsm4(bhh, KhiB + bOff + ks * 32);
            #pragma unroll
            for (int mt = 0; mt < 4; mt++)
                #pragma unroll
                for (int nt = 0; nt < 2; nt++)
                    mmah16816(sacc[mt][nt], ah[mt], &bhh[nt*2]);
        }

        // key-validity of this thread's 4 columns
        const int kb = n0 + wn*16 + cp;
        const bool va = kb < S_, vb2 = kb + 1 < S_;
        const bool vc = kb + 8 < S_, vd = kb + 9 < S_;

        // per-row max: 4 in-thread, then bfly over the 4-lane row group
        #pragma unroll
        for (int mt = 0; mt < 4; mt++) {
            float mlo = fmaxf(fmaxf(va ? sacc[mt][0][0] : -1e30f,
                                    vb2 ? sacc[mt][0][1] : -1e30f),
                              fmaxf(vc ? sacc[mt][1][0] : -1e30f,
                                    vd ? sacc[mt][1][1] : -1e30f));
            float mhi = fmaxf(fmaxf(va ? sacc[mt][0][2] : -1e30f,
                                    vb2 ? sacc[mt][0][3] : -1e30f),
                              fmaxf(vc ? sacc[mt][1][2] : -1e30f,
                                    vd ? sacc[mt][1][3] : -1e30f));
            mlo = fmaxf(mlo, __shfl_xor_sync(0xFFFFFFFFu, mlo, 1));
            mlo = fmaxf(mlo, __shfl_xor_sync(0xFFFFFFFFu, mlo, 2));
            mhi = fmaxf(mhi, __shfl_xor_sync(0xFFFFFFFFu, mhi, 1));
            mhi = fmaxf(mhi, __shfl_xor_sync(0xFFFFFFFFu, mhi, 2));
            int r0 = wm*64 + mt*16 + rg;
            redm[wn*128 + r0]     = mlo;
            redm[wn*128 + r0 + 8] = mhi;
        }
        __syncthreads();
        if (tid < 128) {
            float nm = fmaxf(fmaxf(redm[tid], redm[128 + tid]),
                             fmaxf(redm[256 + tid], redm[384 + tid]));
            nm = fmaxf(nm, m_s[tid]);
            al_s[tid] = __expf(m_s[tid] - nm);
            m_s[tid]  = nm;
        }
        __syncthreads();

        // exp on fragments -> P half2 stores + row sums via bfly
        #pragma unroll
        for (int mt = 0; mt < 4; mt++) {
            int r0 = wm*64 + mt*16 + rg;
            float mlo = m_s[r0], mhi = m_s[r0 + 8];
            float e00 = va  ? __expf(sacc[mt][0][0] - mlo) : 0.f;
            float e01 = vb2 ? __expf(sacc[mt][0][1] - mlo) : 0.f;
            float e10 = vc  ? __expf(sacc[mt][1][0] - mlo) : 0.f;
            float e11 = vd  ? __expf(sacc[mt][1][1] - mlo) : 0.f;
            float f00 = va  ? __expf(sacc[mt][0][2] - mhi) : 0.f;
            float f01 = vb2 ? __expf(sacc[mt][0][3] - mhi) : 0.f;
            float f10 = vc  ? __expf(sacc[mt][1][2] - mhi) : 0.f;
            float f11 = vd  ? __expf(sacc[mt][1][3] - mhi) : 0.f;
            int kc = wn*16 + cp;
            *(__half2*)&Pm[r0*QST + kc] =
                __halves2half2(__float2half_rn(e00), __float2half_rn(e01));
            *(__half2*)&Pm[r0*QST + kc + 8] =
                __halves2half2(__float2half_rn(e10), __float2half_rn(e11));
            *(__half2*)&Pm[(r0+8)*QST + kc] =
                __halves2half2(__float2half_rn(f00), __float2half_rn(f01));
            *(__half2*)&Pm[(r0+8)*QST + kc + 8] =
                __halves2half2(__float2half_rn(f10), __float2half_rn(f11));
            float slo = (e00 + e01) + (e10 + e11);
            float shi = (f00 + f01) + (f10 + f11);
            slo += __shfl_xor_sync(0xFFFFFFFFu, slo, 1);
            slo += __shfl_xor_sync(0xFFFFFFFFu, slo, 2);
            shi += __shfl_xor_sync(0xFFFFFFFFu, shi, 1);
            shi += __shfl_xor_sync(0xFFFFFFFFu, shi, 2);
            reds[wn*128 + r0]     = slo;
            reds[wn*128 + r0 + 8] = shi;
        }

        // rescale O frags by alpha (al_s published 2 barriers ago)
        #pragma unroll
        for (int mt = 0; mt < 4; mt++) {
            float a0 = al_s[wm*64 + mt*16 + rg];
            float a1 = al_s[wm*64 + mt*16 + rg + 8];
            #pragma unroll
            for (int nt = 0; nt < 2; nt++) {
                oacc[mt][nt][0] *= a0; oacc[mt][nt][1] *= a0;
                oacc[mt][nt][2] *= a1; oacc[mt][nt][3] *= a1;
            }
        }
        __syncthreads();   // P + reds visible
        if (tid < 128)
            l_s[tid] = l_s[tid]*al_s[tid] + reds[tid] + reds[128 + tid]
                       + reds[256 + tid] + reds[384 + tid];

        // O += P * V
        #pragma unroll
        for (int ks = 0; ks < 4; ks++) {
            uint32_t ap[4][4], vh[4];
            #pragma unroll
            for (int mt = 0; mt < 4; mt++)
                ldsm4(ap[mt], PmB + aOff + mt * 16 * 144 + ks * 32);
            ldsm4(vh, VhiB + bOff + ks * 32);
            #pragma unroll
            for (int mt = 0; mt < 4; mt++)
                #pragma unroll
                for (int nt = 0; nt < 2; nt++)
                    mmah16816(oacc[mt][nt], ap[mt], &vh[nt*2]);
        }
    }
    __syncthreads();   // final l_s visible

    const int b = bh / H_, h = bh % H_;
    #pragma unroll
    for (int mt = 0; mt < 4; mt++) {
        #pragma unroll
        for (int h2 = 0; h2 < 2; h2++) {
            int q0 = wm*64 + mt*16 + rg + h2*8;
            int m = m0 + q0;
            if (m >= S_) continue;
            float inv = 1.f / l_s[q0];
            #pragma unroll
            for (int nt = 0; nt < 2; nt++) {
                int d0 = wn*16 + nt*8 + cp;
                float w0 = oacc[mt][nt][h2*2 + 0] * inv;
                float w1 = oacc[mt][nt][h2*2 + 1] * inv;
                size_t o = ((size_t)b * S_ + m) * D_ + h * HD_ + d0;
                *(__half2*)&g_aohi[o] = __halves2half2(
                    __float2half_rn(w0), __float2half_rn(w1));
            }
        }
    }
}

// ---------------------------------------------------------------------------
extern "C" void kernel_launch(void* const* d_in, const int* in_sizes, int n_in,
                              void* d_out, int out_size)
{
    const float* x        = (const float*)d_in[0];
    const float* rope_cos = (const float*)d_in[1];
    const float* rope_sin = (const float*)d_in[2];
    const float* Wq       = (const float*)d_in[3];
    const float* bq       = (const float*)d_in[4];
    const float* Wk       = (const float*)d_in[5];
    const float* Wv       = (const float*)d_in[6];
    const float* bv       = (const float*)d_in[7];
    const float* Wo       = (const float*)d_in[8];
    const float* bo       = (const float*)d_in[9];
    float* out = (float*)d_out;

    cudaFuncSetAttribute(attn_kernel,
        cudaFuncAttributeMaxDynamicSharedMemorySize, ATT_SMEM);
    cudaFuncSetAttribute(mma_gemm,
        cudaFuncAttributeMaxDynamicSharedMemorySize, GEMM_SMEM);

    int t4 = M_ * D_ / 4;
    split_act<<<(t4 + 255) / 256, 256>>>(x);

    dim3 wg(32, 32, 4), wb(32, 8);
    split_w<<<wg, wb>>>(Wq, Wk, Wv, Wo);

    // fused QKV projection
    dim3 gq(MPAD / 128, 24);
    mma_gemm<<<gq, 256, GEMM_SMEM>>>(0, 0, bq, bv, nullptr, -1);

    int pairs = B_*H_*S_*16;
    dim3 g2((pairs + 255) / 256, 2);
    rope_kernel<<<g2, 256>>>(rope_cos, rope_sin);

    dim3 g3((S_ + 127) / 128, B_*H_);          // 9 x 128
    attn_kernel<<<g3, 256, ATT_SMEM>>>();

    // output projection
    dim3 go(MPAD / 128, D_ / 128);             // 65 x 8
    mma_gemm<<<go, 256, GEMM_SMEM>>>(1, 3, bo, nullptr, out, 0);
}

// round 15
// speedup vs baseline: 1.3167x; 1.3167x over previous
#include <cuda_runtime.h>
#include <cuda_bf16.h>
#include <cuda_fp16.h>
#include <cstdint>

#define B_    8
#define S_    1029
#define D_    1024
#define H_    16
#define HD_   64
#define M_    (B_*S_)     // 8232
#define MPAD  8320        // 65 * 128
#define NPFX  5
#define SCALE_ 0.125f
#define SVP   1088        // padded key-stride for transposed V

// ---------------------------------------------------------------------------
// Scratch (device globals — no allocation allowed). .bss zero-init.
// ---------------------------------------------------------------------------
__device__ __align__(16) __half g_qh[B_*H_*S_*HD_];     // fp16 Q (rope in place)
__device__ __align__(16) __half g_kh[B_*H_*S_*HD_];     // fp16 K
__device__ __align__(16) __half g_vth[B_*H_*HD_*SVP];   // V^T [b,h,d,s]

__device__ __align__(16) __half g_xhi [MPAD*D_];
__device__ __align__(16) __half g_aohi[MPAD*D_];  // attn out (fp16) [m,n]
__device__ __align__(16) __half g_wthi[4*D_*D_];  // W^T, [w][n][k]

// ---------------------------------------------------------------------------
// mma.sync helpers (portable PTX)
// ---------------------------------------------------------------------------
__device__ __forceinline__ uint32_t smem_u32(const void* p) {
    uint32_t a;
    asm("{ .reg .u64 t; cvta.to.shared.u64 t, %1; cvt.u32.u64 %0, t; }"
        : "=r"(a) : "l"(p));
    return a;
}
__device__ __forceinline__ void ldsm4(uint32_t* r, uint32_t addr) {
    asm volatile("ldmatrix.sync.aligned.m8n8.x4.shared.b16 {%0,%1,%2,%3}, [%4];"
        : "=r"(r[0]), "=r"(r[1]), "=r"(r[2]), "=r"(r[3]) : "r"(addr));
}
__device__ __forceinline__ void mmah16816(float* c, const uint32_t* a,
                                          const uint32_t* b) {
    asm volatile(
        "mma.sync.aligned.m16n8k16.row.col.f32.f16.f16.f32 "
        "{%0,%1,%2,%3}, {%4,%5,%6,%7}, {%8,%9}, {%0,%1,%2,%3};"
        : "+f"(c[0]), "+f"(c[1]), "+f"(c[2]), "+f"(c[3])
        : "r"(a[0]), "r"(a[1]), "r"(a[2]), "r"(a[3]), "r"(b[0]), "r"(b[1]));
}

// ---------------------------------------------------------------------------
// Round x to fp16.
// ---------------------------------------------------------------------------
__global__ void split_act(const float* __restrict__ src)
{
    const int total4 = M_ * D_ / 4;
    int i = blockIdx.x * blockDim.x + threadIdx.x;
    if (i >= total4) return;
    float4 v = ((const float4*)src)[i];
    __half2* Hi = (__half2*)g_xhi;
    Hi[2*i]   = __halves2half2(__float2half_rn(v.x), __float2half_rn(v.y));
    Hi[2*i+1] = __halves2half2(__float2half_rn(v.z), __float2half_rn(v.w));
}

// ---------------------------------------------------------------------------
// Transpose + round all 4 weights (blockIdx.z = widx).
// ---------------------------------------------------------------------------
__global__ void split_w(const float* __restrict__ W0, const float* __restrict__ W1,
                        const float* __restrict__ W2, const float* __restrict__ W3)
{
    __shared__ float t[32][33];
    int widx = blockIdx.z;
    const float* W = (widx == 0) ? W0 : (widx == 1) ? W1 : (widx == 2) ? W2 : W3;
    int n0 = blockIdx.x * 32, k0 = blockIdx.y * 32;
    int tx = threadIdx.x, ty = threadIdx.y;   // 32 x 8
    #pragma unroll
    for (int i = 0; i < 4; i++)
        t[ty + 8*i][tx] = W[(size_t)(k0 + ty + 8*i) * D_ + n0 + tx];
    __syncthreads();
    __half* Hi = g_wthi + (size_t)widx * D_ * D_;
    #pragma unroll
    for (int i = 0; i < 4; i++) {
        float v = t[tx][ty + 8*i];
        Hi[(size_t)(n0 + ty + 8*i) * D_ + k0 + tx] = __float2half_rn(v);
    }
}

// ---------------------------------------------------------------------------
// fp16 tensor-core GEMM: C = A * B. 32 chunks, BK=32, double-buffered 40KB.
// mode 0 -> dst fp32; 1/2 -> g_qh/g_kh fp16; 3 -> fp16 V^T.
// mode == -1: fused QKV; grid.y spans 24, w = by>>3 selects weight & output.
// ---------------------------------------------------------------------------
#define ASTRIDE 40
#define TILEB (128*ASTRIDE)
#define GEMM_SMEM (2*2*TILEB*2)             // 40960 bytes

__global__ __launch_bounds__(256) void mma_gemm(
    int asel, int widx, const float* __restrict__ bq_,
    const float* __restrict__ bv_, float* __restrict__ dst, int mode)
{
    extern __shared__ __half smg[];         // [2][2][TILEB]: A,B

    const int tid  = threadIdx.x;
    const int lane = tid & 31, wid = tid >> 5;
    const int wm = wid & 1, wn = wid >> 1;
    const int bm = blockIdx.x * 128;

    int bn, emode;
    const float* bias;
    if (mode == -1) {               // fused QKV
        int w = blockIdx.y >> 3;
        bn    = (blockIdx.y & 7) * 128;
        widx  = w;
        emode = 1 + w;              // 1=q, 2=k, 3=v
        bias  = (w == 0) ? bq_ : (w == 2) ? bv_ : nullptr;
    } else {
        bn    = blockIdx.y * 128;
        emode = mode;
        bias  = bq_;
    }

    const __half* A = asel ? g_aohi : g_xhi;
    const __half* Bw = g_wthi + (size_t)widx * D_ * D_;

    float acc[4][4][4] = {};

    #pragma unroll
    for (int it = 0; it < 2; it++) {
        int idx = tid + it * 256;
        int r = idx >> 2, c8 = (idx & 3) * 8;
        *(uint4*)&smg[0*TILEB + r*ASTRIDE + c8] =
            *(const uint4*)(A + (size_t)(bm + r) * D_ + c8);
        *(uint4*)&smg[1*TILEB + r*ASTRIDE + c8] =
            *(const uint4*)(Bw + (size_t)(bn + r) * D_ + c8);
    }
    __syncthreads();

    const uint32_t smB = smem_u32(smg);
    const uint32_t aOff = (uint32_t)(wm*64 + (lane & 15)) * 80 + (lane >> 4) * 16;
    const uint32_t bOff = (uint32_t)(wn*32 + (lane & 7) + ((lane >> 4) << 3)) * 80
                          + ((lane >> 3) & 1) * 16;
    const uint32_t TB = TILEB * 2;
    const uint32_t BUFB = 2 * TB;

    const int NCH = 32;
    uint4 p[4];
    for (int t = 0; t < NCH; t++) {
        int buf = t & 1;
        if (t + 1 < NCH) {
            int k0 = (t + 1) * 32;
            #pragma unroll
            for (int it = 0; it < 2; it++) {
                int idx = tid + it * 256;
                int r = idx >> 2, c8 = (idx & 3) * 8;
                p[it*2 + 0] = *(const uint4*)(A  + (size_t)(bm + r) * D_ + k0 + c8);
                p[it*2 + 1] = *(const uint4*)(Bw + (size_t)(bn + r) * D_ + k0 + c8);
            }
        }
        uint32_t aB = smB + buf * BUFB;
        uint32_t bB = aB + TB;
        #pragma unroll
        for (int ks = 0; ks < 2; ks++) {
            uint32_t af[4][4], bf[2][4];
            #pragma unroll
            for (int mt = 0; mt < 4; mt++)
                ldsm4(af[mt], aB + aOff + mt * 16 * 80 + ks * 32);
            #pragma unroll
            for (int bt = 0; bt < 2; bt++)
                ldsm4(bf[bt], bB + bOff + bt * 16 * 80 + ks * 32);
            #pragma unroll
            for (int mt = 0; mt < 4; mt++)
                #pragma unroll
                for (int nt = 0; nt < 4; nt++)
                    mmah16816(acc[mt][nt], af[mt], &bf[nt >> 1][(nt & 1) * 2]);
        }
        if (t + 1 < NCH) {
            int nb = buf ^ 1;
            __half* d0 = smg + nb * 2 * TILEB;
            #pragma unroll
            for (int it = 0; it < 2; it++) {
                int idx = tid + it * 256;
                int r = idx >> 2, c8 = (idx & 3) * 8;
                *(uint4*)&d0[0*TILEB + r*ASTRIDE + c8] = p[it*2 + 0];
                *(uint4*)&d0[1*TILEB + r*ASTRIDE + c8] = p[it*2 + 1];
            }
        }
        __syncthreads();
    }

    const int rg = lane >> 2, cp = (lane & 3) * 2;
    #pragma unroll
    for (int mt = 0; mt < 4; mt++) {
        #pragma unroll
        for (int nt = 0; nt < 4; nt++) {
            int n = bn + wn*32 + nt*8 + cp;
            float b0v = bias ? __ldg(bias + n)     : 0.f;
            float b1v = bias ? __ldg(bias + n + 1) : 0.f;
            #pragma unroll
            for (int h2 = 0; h2 < 2; h2++) {
                int m = bm + wm*64 + mt*16 + rg + h2*8;
                if (m >= M_) continue;
                float v0 = acc[mt][nt][h2*2 + 0] + b0v;
                float v1 = acc[mt][nt][h2*2 + 1] + b1v;
                if (emode == 0) {
                    dst[(size_t)m * D_ + n]     = v0;
                    dst[(size_t)m * D_ + n + 1] = v1;
                } else if (emode == 3) {
                    int b = m / S_, s = m % S_;
                    int h = n >> 6, d = n & 63;
                    size_t o = ((size_t)(b * H_ + h) * HD_ + d) * SVP + s;
                    g_vth[o]       = __float2half_rn(v0);
                    g_vth[o + SVP] = __float2half_rn(v1);
                } else {
                    // q/k: write fp16 pairs (rope applied in place later)
                    int b = m / S_, s = m % S_;
                    int h = n >> 6, d = n & 63;
                    __half* g = (emode == 1) ? g_qh : g_kh;
                    size_t o = (((size_t)(b * H_ + h)) * S_ + s) * HD_ + d;
                    *(__half2*)&g[o] = __halves2half2(
                        __float2half_rn(v0), __float2half_rn(v1));
                }
            }
        }
    }
}

// ---------------------------------------------------------------------------
// In-place fp16 RoPE (patch tokens) + q-scale. Thread owns (d2,d2+1) and
// (d2+32,d2+33) — reads both half2s before writing (in-place safe).
// ---------------------------------------------------------------------------
__global__ void rope_kernel(const float* __restrict__ cosp,
                            const float* __restrict__ sinp)
{
    const int total = B_*H_*S_*16;
    int i = blockIdx.x * blockDim.x + threadIdx.x;
    if (i >= total) return;
    const bool isQ = (blockIdx.y == 0);
    int d2 = (i & 15) * 2;
    int s  = (i >> 4) % S_;
    int bh = i / (16 * S_);
    __half* Hp = (isQ ? g_qh : g_kh) + ((size_t)bh * S_ + s) * HD_;

    __half2 a = *(__half2*)&Hp[d2];
    __half2 b = *(__half2*)&Hp[d2 + 32];
    float x0 = __half2float(__low2half(a)),  x1 = __half2float(__high2half(a));
    float z0 = __half2float(__low2half(b)),  z1 = __half2float(__high2half(b));
    float y0, y1, w0, w1;
    if (s < NPFX) {
        y0 = x0; y1 = x1; w0 = z0; w1 = z1;
    } else {
        int p = s - NPFX;
        float2 cA = *(const float2*)&cosp[p*HD_ + d2];
        float2 cB = *(const float2*)&cosp[p*HD_ + d2 + 32];
        float2 sA = *(const float2*)&sinp[p*HD_ + d2];
        float2 sB = *(const float2*)&sinp[p*HD_ + d2 + 32];
        y0 = x0*cA.x - z0*sA.x;
        y1 = x1*cA.y - z1*sA.y;
        w0 = z0*cB.x + x0*sB.x;
        w1 = z1*cB.y + x1*sB.y;
    }
    if (isQ) { y0 *= SCALE_; y1 *= SCALE_; w0 *= SCALE_; w1 *= SCALE_; }
    *(__half2*)&Hp[d2]      = __halves2half2(__float2half_rn(y0), __float2half_rn(y1));
    *(__half2*)&Hp[d2 + 32] = __halves2half2(__float2half_rn(w0), __float2half_rn(w1));
}

// ---------------------------------------------------------------------------
// Tensor-core flash attention (proven R13 structure: smem S32 softmax).
// 128-q x 64-k tiles, 8 warps in 2(q)x4(k).
// ---------------------------------------------------------------------------
#define QST 72
#define SST 73
#define ATT_SMEM ((128+64+64+128)*QST*2 + 128*SST*4 + (3*128 + 2*256)*4) // 96320

__global__ __launch_bounds__(256) void attn_kernel()
{
    extern __shared__ char smx[];
    __half* Qhi  = (__half*)smx;            // [128][QST]  (q, d)
    __half* Khi  = Qhi  + 128*QST;          // [64][QST]   (key, d)
    __half* Vthi = Khi  + 64*QST;           // [64][QST]   (d, key)
    __half* Pm   = Vthi + 64*QST;           // [128][QST]  (q, key)
    float*  S32  = (float*)(Pm + 128*QST);  // [128][SST]  (q, key)
    float*  m_s  = S32 + 128*SST;           // [128]
    float*  l_s  = m_s + 128;
    float*  al_s = l_s + 128;
    float*  redm = al_s + 128;              // [2][128]
    float*  reds = redm + 256;              // [2][128]

    const int tid  = threadIdx.x;
    const int lane = tid & 31, wid = tid >> 5;
    const int wm = wid & 1, wn = wid >> 1;     // 2(q) x 4(k)
    const int rg = lane >> 2, cp = (lane & 3) * 2;
    const int bh = blockIdx.y;
    const int m0 = blockIdx.x * 128;
    const __half* qhp = g_qh + (size_t)bh * S_ * HD_;
    const __half* khp = g_kh + (size_t)bh * S_ * HD_;
    const __half* vhp = g_vth + (size_t)bh * HD_ * SVP;

    const uint4 Z4 = make_uint4(0u, 0u, 0u, 0u);
    #pragma unroll
    for (int it = 0; it < 4; it++) {
        int idx = tid + it * 256;
        int r = idx >> 3, c8 = (idx & 7) * 8;
        uint4 vh = Z4;
        if (m0 + r < S_)
            vh = *(const uint4*)(qhp + (size_t)(m0 + r) * HD_ + c8);
        *(uint4*)&Qhi[r*QST + c8] = vh;
    }
    if (tid < 128) { m_s[tid] = -1e30f; l_s[tid] = 0.f; }

    const uint32_t QhiB = smem_u32(Qhi);
    const uint32_t KhiB = smem_u32(Khi);
    const uint32_t VhiB = smem_u32(Vthi);
    const uint32_t PmB  = smem_u32(Pm);
    const uint32_t aOff = (uint32_t)(wm*64 + (lane & 15)) * 144 + (lane >> 4) * 16;
    const uint32_t bOff = (uint32_t)(wn*16 + (lane & 7) + ((lane >> 4) << 3)) * 144
                          + ((lane >> 3) & 1) * 16;

    float oacc[4][2][4] = {};
    const int sq = tid & 127, part = tid >> 7;   // 2 partials x 32 keys

    for (int n0 = 0; n0 < S_; n0 += 64) {
        __syncthreads();   // protects K/V/P reuse + first-iter init
        #pragma unroll
        for (int it = 0; it < 2; it++) {
            int idx = tid + it * 256;
            int r = idx >> 3, c8 = (idx & 7) * 8;
            uint4 vh = Z4;
            if (n0 + r < S_)
                vh = *(const uint4*)(khp + (size_t)(n0 + r) * HD_ + c8);
            *(uint4*)&Khi[r*QST + c8] = vh;
        }
        #pragma unroll
        for (int it = 0; it < 2; it++) {
            int idx = tid + it * 256;
            int d = idx >> 3, k8 = (idx & 7) * 8;
            *(uint4*)&Vthi[d*QST + k8] =
                *(const uint4*)(vhp + (size_t)d * SVP + n0 + k8);
        }
        __syncthreads();

        // S = Q K^T
        float sacc[4][2][4] = {};
        #pragma unroll
        for (int ks = 0; ks < 4; ks++) {
            uint32_t ah[4][4], bhh[4];
            #pragma unroll
            for (int mt = 0; mt < 4; mt++)
                ldsm4(ah[mt], QhiB + aOff + mt * 16 * 144 + ks * 32);
            ldsm4(bhh, KhiB + bOff + ks * 32);
            #pragma unroll
            for (int mt = 0; mt < 4; mt++)
                #pragma unroll
                for (int nt = 0; nt < 2; nt++)
                    mmah16816(sacc[mt][nt], ah[mt], &bhh[nt*2]);
        }
        // store S frags
        #pragma unroll
        for (int mt = 0; mt < 4; mt++)
            #pragma unroll
            for (int nt = 0; nt < 2; nt++) {
                int q0 = wm*64 + mt*16 + rg;
                int kc = wn*16 + nt*8 + cp;
                S32[q0*SST + kc]       = sacc[mt][nt][0];
                S32[q0*SST + kc + 1]   = sacc[mt][nt][1];
                S32[(q0+8)*SST + kc]     = sacc[mt][nt][2];
                S32[(q0+8)*SST + kc + 1] = sacc[mt][nt][3];
            }
        __syncthreads();

        // per-query max over this tile (2 partials x 32 keys)
        {
            float pm = -1e30f;
            #pragma unroll
            for (int i = 0; i < 32; i++) {
                int kk = part*32 + i;
                float v = S32[sq*SST + kk];
                pm = fmaxf(pm, (n0 + kk < S_) ? v : -1e30f);
            }
            redm[part*128 + sq] = pm;
        }
        __syncthreads();
        if (tid < 128) {
            float nm = fmaxf(fmaxf(redm[sq], redm[128+sq]), m_s[sq]);
            al_s[sq] = __expf(m_s[sq] - nm);
            m_s[sq]  = nm;
        }
        __syncthreads();
        // exp -> P fp16, partial sums
        {
            float mr = m_s[sq];
            float ps = 0.f;
            #pragma unroll
            for (int i = 0; i < 32; i++) {
                int kk = part*32 + i;
                float e = 0.f;
                if (n0 + kk < S_) e = __expf(S32[sq*SST + kk] - mr);
                Pm[sq*QST + kk] = __float2half_rn(e);
                ps += e;
            }
            reds[part*128 + sq] = ps;
        }
        __syncthreads();
        if (tid < 128)
            l_s[sq] = l_s[sq]*al_s[sq] + reds[sq] + reds[128+sq];

        // rescale O frags by alpha
        #pragma unroll
        for (int mt = 0; mt < 4; mt++) {
            float a0 = al_s[wm*64 + mt*16 + rg];
            float a1 = al_s[wm*64 + mt*16 + rg + 8];
            #pragma unroll
            for (int nt = 0; nt < 2; nt++) {
                oacc[mt][nt][0] *= a0; oacc[mt][nt][1] *= a0;
                oacc[mt][nt][2] *= a1; oacc[mt][nt][3] *= a1;
            }
        }
        // O += P * V
        #pragma unroll
        for (int ks = 0; ks < 4; ks++) {
            uint32_t ap[4][4], vh[4];
            #pragma unroll
            for (int mt = 0; mt < 4; mt++)
                ldsm4(ap[mt], PmB + aOff + mt * 16 * 144 + ks * 32);
            ldsm4(vh, VhiB + bOff + ks * 32);
            #pragma unroll
            for (int mt = 0; mt < 4; mt++)
                #pragma unroll
                for (int nt = 0; nt < 2; nt++)
                    mmah16816(oacc[mt][nt], ap[mt], &vh[nt*2]);
        }
    }
    __syncthreads();   // final l_s visible

    // epilogue: write fp16 ao for the output projection
    const int b = bh / H_, h = bh % H_;
    #pragma unroll
    for (int mt = 0; mt < 4; mt++) {
        #pragma unroll
        for (int h2 = 0; h2 < 2; h2++) {
            int q0 = wm*64 + mt*16 + rg + h2*8;
            int m = m0 + q0;
            if (m >= S_) continue;
            float inv = 1.f / l_s[q0];
            #pragma unroll
            for (int nt = 0; nt < 2; nt++) {
                int d0 = wn*16 + nt*8 + cp;
                float w0 = oacc[mt][nt][h2*2 + 0] * inv;
                float w1 = oacc[mt][nt][h2*2 + 1] * inv;
                size_t o = ((size_t)b * S_ + m) * D_ + h * HD_ + d0;
                *(__half2*)&g_aohi[o] = __halves2half2(
                    __float2half_rn(w0), __float2half_rn(w1));
            }
        }
    }
}

// ---------------------------------------------------------------------------
extern "C" void kernel_launch(void* const* d_in, const int* in_sizes, int n_in,
                              void* d_out, int out_size)
{
    const float* x        = (const float*)d_in[0];
    const float* rope_cos = (const float*)d_in[1];
    const float* rope_sin = (const float*)d_in[2];
    const float* Wq       = (const float*)d_in[3];
    const float* bq       = (const float*)d_in[4];
    const float* Wk       = (const float*)d_in[5];
    const float* Wv       = (const float*)d_in[6];
    const float* bv       = (const float*)d_in[7];
    const float* Wo       = (const float*)d_in[8];
    const float* bo       = (const float*)d_in[9];
    float* out = (float*)d_out;

    cudaFuncSetAttribute(attn_kernel,
        cudaFuncAttributeMaxDynamicSharedMemorySize, ATT_SMEM);
    cudaFuncSetAttribute(mma_gemm,
        cudaFuncAttributeMaxDynamicSharedMemorySize, GEMM_SMEM);

    int t4 = M_ * D_ / 4;
    split_act<<<(t4 + 255) / 256, 256>>>(x);

    dim3 wg(32, 32, 4), wb(32, 8);
    split_w<<<wg, wb>>>(Wq, Wk, Wv, Wo);

    // fused QKV projection
    dim3 gq(MPAD / 128, 24);
    mma_gemm<<<gq, 256, GEMM_SMEM>>>(0, 0, bq, bv, nullptr, -1);

    int pairs = B_*H_*S_*16;
    dim3 g2((pairs + 255) / 256, 2);
    rope_kernel<<<g2, 256>>>(rope_cos, rope_sin);

    dim3 g3((S_ + 127) / 128, B_*H_);          // 9 x 128
    attn_kernel<<<g3, 256, ATT_SMEM>>>();

    // output projection
    dim3 go(MPAD / 128, D_ / 128);             // 65 x 8
    mma_gemm<<<go, 256, GEMM_SMEM>>>(1, 3, bo, nullptr, out, 0);
}

// round 16
// speedup vs baseline: 1.7769x; 1.3495x over previous
#include <cuda_runtime.h>
#include <cuda_bf16.h>
#include <cuda_fp16.h>
#include <cstdint>

#define B_    8
#define S_    1029
#define D_    1024
#define H_    16
#define HD_   64
#define M_    (B_*S_)     // 8232
#define MPAD  8320        // 65 * 128
#define NPFX  5
#define SCALE_ 0.125f
#define SVP   1088        // padded key-stride for transposed V

// ---------------------------------------------------------------------------
// Scratch (device globals — no allocation allowed). .bss zero-init.
// ---------------------------------------------------------------------------
__device__ __align__(16) __half g_qh[B_*H_*S_*HD_];     // fp16 Q (rope in place)
__device__ __align__(16) __half g_kh[B_*H_*S_*HD_];     // fp16 K
__device__ __align__(16) __half g_vth[B_*H_*HD_*SVP];   // V^T [b,h,d,s]

__device__ __align__(16) __half g_xhi [MPAD*D_];
__device__ __align__(16) __half g_aohi[MPAD*D_];  // attn out (fp16) [m,n]
__device__ __align__(16) __half g_wthi[4*D_*D_];  // W^T, [w][n][k]

// ---------------------------------------------------------------------------
// mma.sync helpers (portable PTX)
// ---------------------------------------------------------------------------
__device__ __forceinline__ uint32_t smem_u32(const void* p) {
    uint32_t a;
    asm("{ .reg .u64 t; cvta.to.shared.u64 t, %1; cvt.u32.u64 %0, t; }"
        : "=r"(a) : "l"(p));
    return a;
}
__device__ __forceinline__ void ldsm4(uint32_t* r, uint32_t addr) {
    asm volatile("ldmatrix.sync.aligned.m8n8.x4.shared.b16 {%0,%1,%2,%3}, [%4];"
        : "=r"(r[0]), "=r"(r[1]), "=r"(r[2]), "=r"(r[3]) : "r"(addr));
}
__device__ __forceinline__ void mmah16816(float* c, const uint32_t* a,
                                          const uint32_t* b) {
    asm volatile(
        "mma.sync.aligned.m16n8k16.row.col.f32.f16.f16.f32 "
        "{%0,%1,%2,%3}, {%4,%5,%6,%7}, {%8,%9}, {%0,%1,%2,%3};"
        : "+f"(c[0]), "+f"(c[1]), "+f"(c[2]), "+f"(c[3])
        : "r"(a[0]), "r"(a[1]), "r"(a[2]), "r"(a[3]), "r"(b[0]), "r"(b[1]));
}
__device__ __forceinline__ uint32_t packh2(float a, float b) {
    __half2 h = __halves2half2(__float2half_rn(a), __float2half_rn(b));
    return *(uint32_t*)&h;
}

// ---------------------------------------------------------------------------
// Round x to fp16.
// ---------------------------------------------------------------------------
__global__ void split_act(const float* __restrict__ src)
{
    const int total4 = M_ * D_ / 4;
    int i = blockIdx.x * blockDim.x + threadIdx.x;
    if (i >= total4) return;
    float4 v = ((const float4*)src)[i];
    __half2* Hi = (__half2*)g_xhi;
    Hi[2*i]   = __halves2half2(__float2half_rn(v.x), __float2half_rn(v.y));
    Hi[2*i+1] = __halves2half2(__float2half_rn(v.z), __float2half_rn(v.w));
}

// ---------------------------------------------------------------------------
// Transpose + round all 4 weights (blockIdx.z = widx).
// ---------------------------------------------------------------------------
__global__ void split_w(const float* __restrict__ W0, const float* __restrict__ W1,
                        const float* __restrict__ W2, const float* __restrict__ W3)
{
    __shared__ float t[32][33];
    int widx = blockIdx.z;
    const float* W = (widx == 0) ? W0 : (widx == 1) ? W1 : (widx == 2) ? W2 : W3;
    int n0 = blockIdx.x * 32, k0 = blockIdx.y * 32;
    int tx = threadIdx.x, ty = threadIdx.y;   // 32 x 8
    #pragma unroll
    for (int i = 0; i < 4; i++)
        t[ty + 8*i][tx] = W[(size_t)(k0 + ty + 8*i) * D_ + n0 + tx];
    __syncthreads();
    __half* Hi = g_wthi + (size_t)widx * D_ * D_;
    #pragma unroll
    for (int i = 0; i < 4; i++) {
        float v = t[tx][ty + 8*i];
        Hi[(size_t)(n0 + ty + 8*i) * D_ + k0 + tx] = __float2half_rn(v);
    }
}

// ---------------------------------------------------------------------------
// fp16 tensor-core GEMM (proven R15). 32 chunks, BK=32, double-buffered 40KB.
// mode 0 -> dst fp32; 1/2 -> g_qh/g_kh fp16; 3 -> fp16 V^T.
// mode == -1: fused QKV; grid.y spans 24, w = by>>3 selects weight & output.
// ---------------------------------------------------------------------------
#define ASTRIDE 40
#define TILEB (128*ASTRIDE)
#define GEMM_SMEM (2*2*TILEB*2)             // 40960 bytes

__global__ __launch_bounds__(256) void mma_gemm(
    int asel, int widx, const float* __restrict__ bq_,
    const float* __restrict__ bv_, float* __restrict__ dst, int mode)
{
    extern __shared__ __half smg[];         // [2][2][TILEB]: A,B

    const int tid  = threadIdx.x;
    const int lane = tid & 31, wid = tid >> 5;
    const int wm = wid & 1, wn = wid >> 1;
    const int bm = blockIdx.x * 128;

    int bn, emode;
    const float* bias;
    if (mode == -1) {               // fused QKV
        int w = blockIdx.y >> 3;
        bn    = (blockIdx.y & 7) * 128;
        widx  = w;
        emode = 1 + w;              // 1=q, 2=k, 3=v
        bias  = (w == 0) ? bq_ : (w == 2) ? bv_ : nullptr;
    } else {
        bn    = blockIdx.y * 128;
        emode = mode;
        bias  = bq_;
    }

    const __half* A = asel ? g_aohi : g_xhi;
    const __half* Bw = g_wthi + (size_t)widx * D_ * D_;

    float acc[4][4][4] = {};

    #pragma unroll
    for (int it = 0; it < 2; it++) {
        int idx = tid + it * 256;
        int r = idx >> 2, c8 = (idx & 3) * 8;
        *(uint4*)&smg[0*TILEB + r*ASTRIDE + c8] =
            *(const uint4*)(A + (size_t)(bm + r) * D_ + c8);
        *(uint4*)&smg[1*TILEB + r*ASTRIDE + c8] =
            *(const uint4*)(Bw + (size_t)(bn + r) * D_ + c8);
    }
    __syncthreads();

    const uint32_t smB = smem_u32(smg);
    const uint32_t aOff = (uint32_t)(wm*64 + (lane & 15)) * 80 + (lane >> 4) * 16;
    const uint32_t bOff = (uint32_t)(wn*32 + (lane & 7) + ((lane >> 4) << 3)) * 80
                          + ((lane >> 3) & 1) * 16;
    const uint32_t TB = TILEB * 2;
    const uint32_t BUFB = 2 * TB;

    const int NCH = 32;
    uint4 p[4];
    for (int t = 0; t < NCH; t++) {
        int buf = t & 1;
        if (t + 1 < NCH) {
            int k0 = (t + 1) * 32;
            #pragma unroll
            for (int it = 0; it < 2; it++) {
                int idx = tid + it * 256;
                int r = idx >> 2, c8 = (idx & 3) * 8;
                p[it*2 + 0] = *(const uint4*)(A  + (size_t)(bm + r) * D_ + k0 + c8);
                p[it*2 + 1] = *(const uint4*)(Bw + (size_t)(bn + r) * D_ + k0 + c8);
            }
        }
        uint32_t aB = smB + buf * BUFB;
        uint32_t bB = aB + TB;
        #pragma unroll
        for (int ks = 0; ks < 2; ks++) {
            uint32_t af[4][4], bf[2][4];
            #pragma unroll
            for (int mt = 0; mt < 4; mt++)
                ldsm4(af[mt], aB + aOff + mt * 16 * 80 + ks * 32);
            #pragma unroll
            for (int bt = 0; bt < 2; bt++)
                ldsm4(bf[bt], bB + bOff + bt * 16 * 80 + ks * 32);
            #pragma unroll
            for (int mt = 0; mt < 4; mt++)
                #pragma unroll
                for (int nt = 0; nt < 4; nt++)
                    mmah16816(acc[mt][nt], af[mt], &bf[nt >> 1][(nt & 1) * 2]);
        }
        if (t + 1 < NCH) {
            int nb = buf ^ 1;
            __half* d0 = smg + nb * 2 * TILEB;
            #pragma unroll
            for (int it = 0; it < 2; it++) {
                int idx = tid + it * 256;
                int r = idx >> 2, c8 = (idx & 3) * 8;
                *(uint4*)&d0[0*TILEB + r*ASTRIDE + c8] = p[it*2 + 0];
                *(uint4*)&d0[1*TILEB + r*ASTRIDE + c8] = p[it*2 + 1];
            }
        }
        __syncthreads();
    }

    const int rg = lane >> 2, cp = (lane & 3) * 2;
    #pragma unroll
    for (int mt = 0; mt < 4; mt++) {
        #pragma unroll
        for (int nt = 0; nt < 4; nt++) {
            int n = bn + wn*32 + nt*8 + cp;
            float b0v = bias ? __ldg(bias + n)     : 0.f;
            float b1v = bias ? __ldg(bias + n + 1) : 0.f;
            #pragma unroll
            for (int h2 = 0; h2 < 2; h2++) {
                int m = bm + wm*64 + mt*16 + rg + h2*8;
                if (m >= M_) continue;
                float v0 = acc[mt][nt][h2*2 + 0] + b0v;
                float v1 = acc[mt][nt][h2*2 + 1] + b1v;
                if (emode == 0) {
                    dst[(size_t)m * D_ + n]     = v0;
                    dst[(size_t)m * D_ + n + 1] = v1;
                } else if (emode == 3) {
                    int b = m / S_, s = m % S_;
                    int h = n >> 6, d = n & 63;
                    size_t o = ((size_t)(b * H_ + h) * HD_ + d) * SVP + s;
                    g_vth[o]       = __float2half_rn(v0);
                    g_vth[o + SVP] = __float2half_rn(v1);
                } else {
                    int b = m / S_, s = m % S_;
                    int h = n >> 6, d = n & 63;
                    __half* g = (emode == 1) ? g_qh : g_kh;
                    size_t o = (((size_t)(b * H_ + h)) * S_ + s) * HD_ + d;
                    *(__half2*)&g[o] = __halves2half2(
                        __float2half_rn(v0), __float2half_rn(v1));
                }
            }
        }
    }
}

// ---------------------------------------------------------------------------
// In-place fp16 RoPE (patch tokens) + q-scale.
// ---------------------------------------------------------------------------
__global__ void rope_kernel(const float* __restrict__ cosp,
                            const float* __restrict__ sinp)
{
    const int total = B_*H_*S_*16;
    int i = blockIdx.x * blockDim.x + threadIdx.x;
    if (i >= total) return;
    const bool isQ = (blockIdx.y == 0);
    int d2 = (i & 15) * 2;
    int s  = (i >> 4) % S_;
    int bh = i / (16 * S_);
    __half* Hp = (isQ ? g_qh : g_kh) + ((size_t)bh * S_ + s) * HD_;

    __half2 a = *(__half2*)&Hp[d2];
    __half2 b = *(__half2*)&Hp[d2 + 32];
    float x0 = __half2float(__low2half(a)),  x1 = __half2float(__high2half(a));
    float z0 = __half2float(__low2half(b)),  z1 = __half2float(__high2half(b));
    float y0, y1, w0, w1;
    if (s < NPFX) {
        y0 = x0; y1 = x1; w0 = z0; w1 = z1;
    } else {
        int p = s - NPFX;
        float2 cA = *(const float2*)&cosp[p*HD_ + d2];
        float2 cB = *(const float2*)&cosp[p*HD_ + d2 + 32];
        float2 sA = *(const float2*)&sinp[p*HD_ + d2];
        float2 sB = *(const float2*)&sinp[p*HD_ + d2 + 32];
        y0 = x0*cA.x - z0*sA.x;
        y1 = x1*cA.y - z1*sA.y;
        w0 = z0*cB.x + x0*sB.x;
        w1 = z1*cB.y + x1*sB.y;
    }
    if (isQ) { y0 *= SCALE_; y1 *= SCALE_; w0 *= SCALE_; w1 *= SCALE_; }
    *(__half2*)&Hp[d2]      = __halves2half2(__float2half_rn(y0), __float2half_rn(y1));
    *(__half2*)&Hp[d2 + 32] = __halves2half2(__float2half_rn(w0), __float2half_rn(w1));
}

// ---------------------------------------------------------------------------
// FA2-style tensor-core flash attention: 128-q x 64-k tiles, 8 warps each
// owning 16 q rows. P stays in registers (QK C-frag == PV A-frag layout);
// softmax is warp-local (4-lane bfly) — no S/P smem, 2 barriers per tile.
// ---------------------------------------------------------------------------
#define QST 72
#define ATT_SMEM ((128+64+64)*QST*2)   // 36864

__global__ __launch_bounds__(256) void attn_kernel()
{
    extern __shared__ char smx[];
    __half* Qhi  = (__half*)smx;            // [128][QST]  (q, d)
    __half* Khi  = Qhi + 128*QST;           // [64][QST]   (key, d)
    __half* Vthi = Khi + 64*QST;            // [64][QST]   (d, key)

    const int tid  = threadIdx.x;
    const int lane = tid & 31, wid = tid >> 5;
    const int rg = lane >> 2, cp = (lane & 3) * 2;
    const int bh = blockIdx.y;
    const int m0 = blockIdx.x * 128;
    const __half* qhp = g_qh + (size_t)bh * S_ * HD_;
    const __half* khp = g_kh + (size_t)bh * S_ * HD_;
    const __half* vhp = g_vth + (size_t)bh * HD_ * SVP;

    const uint4 Z4 = make_uint4(0u, 0u, 0u, 0u);
    #pragma unroll
    for (int it = 0; it < 4; it++) {
        int idx = tid + it * 256;
        int r = idx >> 3, c8 = (idx & 7) * 8;
        uint4 vh = Z4;
        if (m0 + r < S_)
            vh = *(const uint4*)(qhp + (size_t)(m0 + r) * HD_ + c8);
        *(uint4*)&Qhi[r*QST + c8] = vh;
    }

    const uint32_t QB = smem_u32(Qhi);
    const uint32_t KB = smem_u32(Khi);
    const uint32_t VB = smem_u32(Vthi);
    const uint32_t aOffQ = (uint32_t)(wid*16 + (lane & 15)) * 144 + (lane >> 4) * 16;
    const uint32_t bOffB = (uint32_t)((lane & 7) + ((lane >> 4) << 3)) * 144
                           + ((lane >> 3) & 1) * 16;

    float oacc[8][4] = {};
    float mr0 = -1e30f, mr1 = -1e30f;      // running max, rows rg / rg+8
    float lr0 = 0.f,    lr1 = 0.f;         // running sum

    for (int n0 = 0; n0 < S_; n0 += 64) {
        __syncthreads();   // protects K/V reuse (and Q on first iter path)
        #pragma unroll
        for (int it = 0; it < 2; it++) {
            int idx = tid + it * 256;
            int r = idx >> 3, c8 = (idx & 7) * 8;
            uint4 vh = Z4;
            if (n0 + r < S_)
                vh = *(const uint4*)(khp + (size_t)(n0 + r) * HD_ + c8);
            *(uint4*)&Khi[r*QST + c8] = vh;
        }
        #pragma unroll
        for (int it = 0; it < 2; it++) {
            int idx = tid + it * 256;
            int d = idx >> 3, k8 = (idx & 7) * 8;
            *(uint4*)&Vthi[d*QST + k8] =
                *(const uint4*)(vhp + (size_t)d * SVP + n0 + k8);
        }
        __syncthreads();

        // S = Q K^T : sacc[j] covers keys 8j..8j+7 for this warp's 16 q rows
        float sacc[8][4] = {};
        #pragma unroll
        for (int ks = 0; ks < 4; ks++) {
            uint32_t aq[4];
            ldsm4(aq, QB + aOffQ + ks * 32);
            #pragma unroll
            for (int jj = 0; jj < 4; jj++) {
                uint32_t bf[4];
                ldsm4(bf, KB + bOffB + jj * 16 * 144 + ks * 32);
                mmah16816(sacc[2*jj],     aq, &bf[0]);
                mmah16816(sacc[2*jj + 1], aq, &bf[2]);
            }
        }

        // mask invalid keys, in-thread max, bfly over the 4-lane row group
        float mlo = -1e30f, mhi = -1e30f;
        #pragma unroll
        for (int j = 0; j < 8; j++) {
            bool v0 = (n0 + 8*j + cp)     < S_;
            bool v1 = (n0 + 8*j + cp + 1) < S_;
            if (!v0) { sacc[j][0] = -1e30f; sacc[j][2] = -1e30f; }
            if (!v1) { sacc[j][1] = -1e30f; sacc[j][3] = -1e30f; }
            mlo = fmaxf(mlo, fmaxf(sacc[j][0], sacc[j][1]));
            mhi = fmaxf(mhi, fmaxf(sacc[j][2], sacc[j][3]));
        }
        mlo = fmaxf(mlo, __shfl_xor_sync(0xFFFFFFFFu, mlo, 1));
        mlo = fmaxf(mlo, __shfl_xor_sync(0xFFFFFFFFu, mlo, 2));
        mhi = fmaxf(mhi, __shfl_xor_sync(0xFFFFFFFFu, mhi, 1));
        mhi = fmaxf(mhi, __shfl_xor_sync(0xFFFFFFFFu, mhi, 2));
        float nm0 = fmaxf(mr0, mlo), nm1 = fmaxf(mr1, mhi);
        float al0 = __expf(mr0 - nm0), al1 = __expf(mr1 - nm1);
        mr0 = nm0; mr1 = nm1;

        // exp -> P fragments (registers) + row sums
        uint32_t pa[4][4];
        float s0 = 0.f, s1 = 0.f;
        #pragma unroll
        for (int j = 0; j < 8; j++) {
            float e0 = __expf(sacc[j][0] - mr0);
            float e1 = __expf(sacc[j][1] - mr0);
            float e2 = __expf(sacc[j][2] - mr1);
            float e3 = __expf(sacc[j][3] - mr1);
            s0 += e0 + e1;
            s1 += e2 + e3;
            int ks = j >> 1, hf = (j & 1) * 2;
            pa[ks][hf + 0] = packh2(e0, e1);
            pa[ks][hf + 1] = packh2(e2, e3);
        }
        s0 += __shfl_xor_sync(0xFFFFFFFFu, s0, 1);
        s0 += __shfl_xor_sync(0xFFFFFFFFu, s0, 2);
        s1 += __shfl_xor_sync(0xFFFFFFFFu, s1, 1);
        s1 += __shfl_xor_sync(0xFFFFFFFFu, s1, 2);
        lr0 = lr0 * al0 + s0;
        lr1 = lr1 * al1 + s1;

        // rescale O
        #pragma unroll
        for (int j = 0; j < 8; j++) {
            oacc[j][0] *= al0; oacc[j][1] *= al0;
            oacc[j][2] *= al1; oacc[j][3] *= al1;
        }
        // O += P * V  (A = P registers, B = V^T tiles)
        #pragma unroll
        for (int ks = 0; ks < 4; ks++) {
            #pragma unroll
            for (int jj = 0; jj < 4; jj++) {
                uint32_t bf[4];
                ldsm4(bf, VB + bOffB + jj * 16 * 144 + ks * 32);
                mmah16816(oacc[2*jj],     pa[ks], &bf[0]);
                mmah16816(oacc[2*jj + 1], pa[ks], &bf[2]);
            }
        }
    }

    // epilogue: write fp16 ao for the output projection
    const int b = bh / H_, h = bh % H_;
    const int q0 = wid*16 + rg;
    const int q1 = q0 + 8;
    const float inv0 = 1.f / lr0;
    const float inv1 = 1.f / lr1;
    #pragma unroll
    for (int j = 0; j < 8; j++) {
        int d0 = 8*j + cp;
        int mA = m0 + q0;
        if (mA < S_) {
            size_t o = ((size_t)b * S_ + mA) * D_ + h * HD_ + d0;
            *(__half2*)&g_aohi[o] = __halves2half2(
                __float2half_rn(oacc[j][0] * inv0),
                __float2half_rn(oacc[j][1] * inv0));
        }
        int mB = m0 + q1;
        if (mB < S_) {
            size_t o = ((size_t)b * S_ + mB) * D_ + h * HD_ + d0;
            *(__half2*)&g_aohi[o] = __halves2half2(
                __float2half_rn(oacc[j][2] * inv1),
                __float2half_rn(oacc[j][3] * inv1));
        }
    }
}

// ---------------------------------------------------------------------------
extern "C" void kernel_launch(void* const* d_in, const int* in_sizes, int n_in,
                              void* d_out, int out_size)
{
    const float* x        = (const float*)d_in[0];
    const float* rope_cos = (const float*)d_in[1];
    const float* rope_sin = (const float*)d_in[2];
    const float* Wq       = (const float*)d_in[3];
    const float* bq       = (const float*)d_in[4];
    const float* Wk       = (const float*)d_in[5];
    const float* Wv       = (const float*)d_in[6];
    const float* bv       = (const float*)d_in[7];
    const float* Wo       = (const float*)d_in[8];
    const float* bo       = (const float*)d_in[9];
    float* out = (float*)d_out;

    cudaFuncSetAttribute(attn_kernel,
        cudaFuncAttributeMaxDynamicSharedMemorySize, ATT_SMEM);
    cudaFuncSetAttribute(mma_gemm,
        cudaFuncAttributeMaxDynamicSharedMemorySize, GEMM_SMEM);

    int t4 = M_ * D_ / 4;
    split_act<<<(t4 + 255) / 256, 256>>>(x);

    dim3 wg(32, 32, 4), wb(32, 8);
    split_w<<<wg, wb>>>(Wq, Wk, Wv, Wo);

    // fused QKV projection
    dim3 gq(MPAD / 128, 24);
    mma_gemm<<<gq, 256, GEMM_SMEM>>>(0, 0, bq, bv, nullptr, -1);

    int pairs = B_*H_*S_*16;
    dim3 g2((pairs + 255) / 256, 2);
    rope_kernel<<<g2, 256>>>(rope_cos, rope_sin);

    dim3 g3((S_ + 127) / 128, B_*H_);          // 9 x 128
    attn_kernel<<<g3, 256, ATT_SMEM>>>();

    // output projection
    dim3 go(MPAD / 128, D_ / 128);             // 65 x 8
    mma_gemm<<<go, 256, GEMM_SMEM>>>(1, 3, bo, nullptr, out, 0);
}